// round 12
// baseline (speedup 1.0000x reference)
#include <cuda_runtime.h>
#include <stdint.h>

// SuperDCFrontShareLayer — confirmed contract:
//   out (float32, 33,554,432) = real part of complex reference
//   out[r][c] = s[c] * x[r][c];  s[0]=s[1023]=1, s[c]=w[(c-1)>>1] otherwise.
//
// Status: kernel pinned at 36.3-37.1us across all R7-R10 variants =
// ~7.35 TB/s sustained (~92% of HBM spec). R11: persistent grid-stride
// kernel — exactly one wave (148 SM x 8 CTA = 1184 blocks), scale table
// loaded once per thread and hoisted (stride is a multiple of 256 so
// i mod 256 == threadIdx.x is loop-invariant), unroll-4 loop body.

static constexpr long long ROWS = 32768;
static constexpr long long COLS = 1024;
static constexpr long long N_OUT = ROWS * COLS;          // 33,554,432 floats
static constexpr unsigned  N4 = (unsigned)(N_OUT / 4);   // 8,388,608 float4
static constexpr unsigned  PERSIST_BLOCKS = 148u * 8u;   // 1184 (one full wave)
static constexpr unsigned  STRIDE = PERSIST_BLOCKS * 256u;  // 303,104 (mult of 256)
static constexpr int NW = 511;

__global__ void __launch_bounds__(256)
scale_persist_kernel(const float4* __restrict__ x, float4* __restrict__ out,
                     const float* __restrict__ w) {
    unsigned m = threadIdx.x;                    // column group, loop-invariant
    unsigned i0 = blockIdx.x * 256u + m;

    // Column scales for columns 4m..4m+3 — loaded ONCE per thread.
    float4 s;
    s.y = __ldg(w + 2 * m);
    s.z = s.y;
    s.x = (m == 0u)   ? 1.0f : __ldg(w + 2 * m - 1);
    s.w = (m == 255u) ? 1.0f : __ldg(w + 2 * m + 1);

    // Grid-stride loop; unroll 4 -> 4 independent in-flight LDG.128 per thread.
    #pragma unroll 4
    for (unsigned i = i0; i < N4; i += STRIDE) {
        float4 v = __ldcs(x + i);                // touch-once: evict-first
        v.x *= s.x; v.y *= s.y; v.z *= s.z; v.w *= s.w;
        out[i] = v;                              // default store: L2 buffers
    }
}

// ---- defensive fallback (unexpected sizes/alignment) ----
__device__ float g_s[COLS];

__global__ void build_scale_kernel(const float* __restrict__ w) {
    int c = blockIdx.x * blockDim.x + threadIdx.x;
    if (c < COLS)
        g_s[c] = (c == 0 || c == COLS - 1) ? 1.0f : w[(c - 1) >> 1];
}

__global__ void __launch_bounds__(256)
scale_scalar_kernel(const float* __restrict__ x, float* __restrict__ out,
                    long long n) {
    long long i = (long long)blockIdx.x * blockDim.x + threadIdx.x;
    if (i < n) out[i] = x[i] * g_s[i & (COLS - 1)];
}

extern "C" void kernel_launch(void* const* d_in, const int* in_sizes, int n_in,
                              void* d_out, int out_size) {
    const float* x = nullptr;
    const float* w = nullptr;
    for (int i = 0; i < n_in; i++) {
        long long sz = in_sizes[i];
        if (sz == N_OUT)   x = (const float*)d_in[i];
        else if (sz == NW) w = (const float*)d_in[i];
    }
    if (!x && n_in >= 1) x = (const float*)d_in[0];
    if (!w && n_in >= 2) w = (const float*)d_in[1];
    if (!x || !w) return;

    long long n = (long long)out_size;
    if (n > N_OUT) n = N_OUT;
    if (n <= 0) return;

    bool fast = (n == N_OUT) &&
                (((((uintptr_t)x) | ((uintptr_t)d_out)) & 15) == 0);
    if (fast) {
        // One persistent wave: 1184 blocks x 256 threads, ~28 float4 per thread.
        scale_persist_kernel<<<PERSIST_BLOCKS, 256>>>(
            (const float4*)x, (float4*)d_out, w);
    } else {
        build_scale_kernel<<<4, 256>>>(w);
        scale_scalar_kernel<<<(unsigned)((n + 255) / 256), 256>>>(
            x, (float*)d_out, n);
    }
}

// round 13
// speedup vs baseline: 1.0497x; 1.0497x over previous
#include <cuda_runtime.h>
#include <stdint.h>

// SuperDCFrontShareLayer — confirmed contract:
//   out (float32, 33,554,432) = real part of complex reference
//   out[r][c] = s[c] * x[r][c];  s[0]=s[1023]=1, s[c]=w[(c-1)>>1] otherwise.
//
// FINAL FORM (= R9, best measured kernel 36.32us, DRAM 73.9%):
//   - single fused kernel; 2KB scale table derived in-kernel (L1-resident)
//   - x2 split-half unroll: 2 independent LDG.128 per thread (MLP 2)
//   - __ldcs reads (touch-once, evict-first), default stores (L2 buffers)
//   - 16384 blocks x 256 threads; block covers one 1024-column period
// Measured roofline: 268MB @ ~7.35 TB/s sustained (~92% of HBM3e spec).
// Explored and rejected: x1 (39.5us), x4+stcs (37.1us), 512-thr (36.5us),
// persistent 1-wave grid (38.8us — oversubscription IS the prefetcher).

static constexpr long long ROWS = 32768;
static constexpr long long COLS = 1024;
static constexpr long long N_OUT = ROWS * COLS;      // 33,554,432 floats
static constexpr long long N4 = N_OUT / 4;           // 8,388,608 float4
static constexpr long long HALF4 = N4 / 2;           // 4,194,304 (multiple of 256)
static constexpr int NW = 511;

__global__ void __launch_bounds__(256)
scale_fused_kernel(const float4* __restrict__ x, float4* __restrict__ out,
                   const float* __restrict__ w) {
    int m = threadIdx.x;                                   // 0..255 == column group
    long long i = (long long)blockIdx.x * 256 + m;

    // Column scales for columns 4m..4m+3 (2KB table, L1-resident).
    float4 s;
    s.y = __ldg(w + 2 * m);
    s.z = s.y;
    s.x = (m == 0)   ? 1.0f : __ldg(w + 2 * m - 1);
    s.w = (m == 255) ? 1.0f : __ldg(w + 2 * m + 1);

    // 2 independent streaming loads (front-batched -> MLP 2).
    float4 v0 = __ldcs(x + i);
    float4 v1 = __ldcs(x + i + HALF4);

    v0.x *= s.x; v0.y *= s.y; v0.z *= s.z; v0.w *= s.w;
    v1.x *= s.x; v1.y *= s.y; v1.z *= s.z; v1.w *= s.w;

    // Default stores: L2 absorbs and streams out to HBM.
    out[i] = v0;
    out[i + HALF4] = v1;
}

// ---- defensive fallback (unexpected sizes/alignment) ----
__device__ float g_s[COLS];

__global__ void build_scale_kernel(const float* __restrict__ w) {
    int c = blockIdx.x * blockDim.x + threadIdx.x;
    if (c < COLS)
        g_s[c] = (c == 0 || c == COLS - 1) ? 1.0f : w[(c - 1) >> 1];
}

__global__ void __launch_bounds__(256)
scale_scalar_kernel(const float* __restrict__ x, float* __restrict__ out,
                    long long n) {
    long long i = (long long)blockIdx.x * blockDim.x + threadIdx.x;
    if (i < n) out[i] = x[i] * g_s[i & (COLS - 1)];
}

extern "C" void kernel_launch(void* const* d_in, const int* in_sizes, int n_in,
                              void* d_out, int out_size) {
    const float* x = nullptr;
    const float* w = nullptr;
    for (int i = 0; i < n_in; i++) {
        long long sz = in_sizes[i];
        if (sz == N_OUT)   x = (const float*)d_in[i];
        else if (sz == NW) w = (const float*)d_in[i];
    }
    if (!x && n_in >= 1) x = (const float*)d_in[0];
    if (!w && n_in >= 2) w = (const float*)d_in[1];
    if (!x || !w) return;

    long long n = (long long)out_size;
    if (n > N_OUT) n = N_OUT;
    if (n <= 0) return;

    bool fast = (n == N_OUT) &&
                (((((uintptr_t)x) | ((uintptr_t)d_out)) & 15) == 0);
    if (fast) {
        // 16384 blocks x 256 threads; each thread: 2 float4 in, 2 float4 out.
        scale_fused_kernel<<<(unsigned)(HALF4 / 256), 256>>>(
            (const float4*)x, (float4*)d_out, w);
    } else {
        build_scale_kernel<<<4, 256>>>(w);
        scale_scalar_kernel<<<(unsigned)((n + 255) / 256), 256>>>(
            x, (float*)d_out, n);
    }
}

// round 14
// speedup vs baseline: 1.0883x; 1.0368x over previous
#include <cuda_runtime.h>
#include <stdint.h>

// SuperDCFrontShareLayer — confirmed contract:
//   out (float32, 33,554,432) = real part of complex reference
//   out[r][c] = s[c] * x[r][c];  s[0]=s[1023]=1, s[c]=w[(c-1)>>1] otherwise.
//
// R13: last untested plateau cell — R9 structure (x2 split-half, 16384x256,
// __ldcs reads) + __stcs STORES (evict-first write stream: keep 128MB of
// touch-once dirty lines from cycling L2's LRU; shortens the dirty-writeback
// tail between graph replays). Kernel-window time predicted unchanged
// (roofline: 268MB @ ~7.35 TB/s sustained, ~92% of HBM3e spec).
// Matrix so far: x1 39.5 | x2 36.32 (best) | x4+stcs 37.1 | 512thr 36.5 |
// persistent 38.8.

static constexpr long long ROWS = 32768;
static constexpr long long COLS = 1024;
static constexpr long long N_OUT = ROWS * COLS;      // 33,554,432 floats
static constexpr long long N4 = N_OUT / 4;           // 8,388,608 float4
static constexpr long long HALF4 = N4 / 2;           // 4,194,304 (multiple of 256)
static constexpr int NW = 511;

__global__ void __launch_bounds__(256)
scale_fused_kernel(const float4* __restrict__ x, float4* __restrict__ out,
                   const float* __restrict__ w) {
    int m = threadIdx.x;                                   // 0..255 == column group
    long long i = (long long)blockIdx.x * 256 + m;

    // Column scales for columns 4m..4m+3 (2KB table, L1-resident).
    float4 s;
    s.y = __ldg(w + 2 * m);
    s.z = s.y;
    s.x = (m == 0)   ? 1.0f : __ldg(w + 2 * m - 1);
    s.w = (m == 255) ? 1.0f : __ldg(w + 2 * m + 1);

    // 2 independent streaming loads (front-batched -> MLP 2).
    float4 v0 = __ldcs(x + i);
    float4 v1 = __ldcs(x + i + HALF4);

    v0.x *= s.x; v0.y *= s.y; v0.z *= s.z; v0.w *= s.w;
    v1.x *= s.x; v1.y *= s.y; v1.z *= s.z; v1.w *= s.w;

    // Evict-first stores: touch-once write stream stays out of L2's LRU.
    __stcs(out + i,         v0);
    __stcs(out + i + HALF4, v1);
}

// ---- defensive fallback (unexpected sizes/alignment) ----
__device__ float g_s[COLS];

__global__ void build_scale_kernel(const float* __restrict__ w) {
    int c = blockIdx.x * blockDim.x + threadIdx.x;
    if (c < COLS)
        g_s[c] = (c == 0 || c == COLS - 1) ? 1.0f : w[(c - 1) >> 1];
}

__global__ void __launch_bounds__(256)
scale_scalar_kernel(const float* __restrict__ x, float* __restrict__ out,
                    long long n) {
    long long i = (long long)blockIdx.x * blockDim.x + threadIdx.x;
    if (i < n) out[i] = x[i] * g_s[i & (COLS - 1)];
}

extern "C" void kernel_launch(void* const* d_in, const int* in_sizes, int n_in,
                              void* d_out, int out_size) {
    const float* x = nullptr;
    const float* w = nullptr;
    for (int i = 0; i < n_in; i++) {
        long long sz = in_sizes[i];
        if (sz == N_OUT)   x = (const float*)d_in[i];
        else if (sz == NW) w = (const float*)d_in[i];
    }
    if (!x && n_in >= 1) x = (const float*)d_in[0];
    if (!w && n_in >= 2) w = (const float*)d_in[1];
    if (!x || !w) return;

    long long n = (long long)out_size;
    if (n > N_OUT) n = N_OUT;
    if (n <= 0) return;

    bool fast = (n == N_OUT) &&
                (((((uintptr_t)x) | ((uintptr_t)d_out)) & 15) == 0);
    if (fast) {
        // 16384 blocks x 256 threads; each thread: 2 float4 in, 2 float4 out.
        scale_fused_kernel<<<(unsigned)(HALF4 / 256), 256>>>(
            (const float4*)x, (float4*)d_out, w);
    } else {
        build_scale_kernel<<<4, 256>>>(w);
        scale_scalar_kernel<<<(unsigned)((n + 255) / 256), 256>>>(
            x, (float*)d_out, n);
    }
}